// round 5
// baseline (speedup 1.0000x reference)
#include <cuda_runtime.h>
#include <math.h>

// Scratch for per-utterance total scores (no cudaMalloc allowed).
#define MAX_B 4096
__device__ float g_tot[MAX_B];

// One CTA per batch element. Thread s owns CTC state s (S = 2L+1 states).
// Linear-domain forward with PER-WARP exact power-of-two scaling: the alpha
// spread across all S states (~200+ nats) exceeds fp32 range, but the spread
// within one warp (32 adjacent states) is only ~30-45 binary orders.
__global__ void ctc_scan_kernel(const float* __restrict__ lp,
                                const int* __restrict__ targets,
                                const int* __restrict__ ilen,
                                int B, int V, int L) {
  const int b = blockIdx.x;
  const int S = 2 * L + 1;
  const int s = threadIdx.x;
  const int NT = blockDim.x;
  const int NW = NT >> 5;
  const int lane = s & 31;
  const int wid = s >> 5;

  extern __shared__ float sh[];
  float* bufA = sh;                          // NT+2 floats; state s at index 2+s
  float* bufB = sh + (NT + 2);               // NT+2 floats
  float* fin  = sh + 2 * (NT + 2);           // 2 floats (final readout)
  int*   sE   = (int*)(sh + 2 * (NT + 2) + 2);  // NW ints: published Ecum per warp

  const bool valid = (s < S);
  const float validf = valid ? 1.0f : 0.0f;  // phantom states pinned to 0
  int label = 0;        // blank = 0 for even states and phantom threads
  float skipw = 0.0f;   // 1.0 iff skip transition s-2 -> s allowed
  if (valid && (s & 1)) {
    const int l = s >> 1;
    label = targets[b * L + l];
    if (s >= 2 && label != targets[b * L + l - 1]) skipw = 1.0f;
  }

  const float* eptr = lp + (size_t)b * V + label;
  const size_t stride = (size_t)B * V;
  const int len = ilen[b];

  // t = 0 init: alpha[0] = p(blank), alpha[1] = p(label0), rest 0.
  float a = 0.0f;
  if (s < 2) a = __expf(__ldg(eptr));
  if (s < 2) { bufA[s] = 0.0f; bufB[s] = 0.0f; }  // pads = 0 in linear domain
  bufA[2 + s] = a;
  if (lane == 0) sE[wid] = 0;
  int Ecum = 0;  // true_alpha = stored_alpha * 2^{Ecum}  (warp-uniform)

  const int G = 8;
  float lpv[G];
#pragma unroll
  for (int j = 0; j < G; j++) {
    const int t = 1 + j;
    lpv[j] = (t < len) ? __ldg(eptr + (size_t)t * stride) : 0.0f;
  }
  __syncthreads();

// One step: a = (a + m1*a1 + m2s*a2) * pv. m1/m2s carry the cross-warp scale
// conversion for lanes 0/1 (=1/skipw for interior lanes). Guard is block-uniform.
#define CTC_STEP(j, RD, WR)                         \
    if (tb + (j) < len) {                           \
      float t1 = fmaf(m1, RD[2 + s - 1], a);        \
      a = fmaf(m2s, RD[2 + s - 2], t1) * pv[j];     \
      WR[2 + s] = a;                                \
      __syncthreads();                              \
    }

  for (int tb = 1; tb < len; tb += G) {
    // ---- Phase A: per-warp rescale to put warp max at ~2^30, publish Ecum.
    const unsigned u = __reduce_max_sync(0xffffffffu, __float_as_uint(a));
    if (u != 0u) {
      const int e = (int)((u >> 23) & 255u) - 127;
      int k = 30 - e;
      k = k > 127 ? 127 : (k < -126 ? -126 : k);
      a *= __int_as_float((127 + k) << 23);  // exact power of two
      Ecum -= k;
      if (lane == 0) sE[wid] = Ecum;
    }
    bufA[2 + s] = a;  // window always starts reading bufA (8 steps/window)

    // Prefetch next group's emissions; exponentiate this group's (off chain).
    float lpn[G];
#pragma unroll
    for (int j = 0; j < G; j++) {
      const int t = tb + G + j;
      lpn[j] = (t < len) ? __ldg(eptr + (size_t)t * stride) : 0.0f;
    }
    float pv[G];
#pragma unroll
    for (int j = 0; j < G; j++) pv[j] = __expf(lpv[j]) * validf;

    __syncthreads();

    // ---- Phase B: read neighbor's published scale, build boundary factor.
    const int nbr = (wid > 0) ? sE[wid - 1] : Ecum;
    if (u == 0u) Ecum = nbr;  // empty warp adopts neighbor scale (dE -> 0)
    int dE = nbr - Ecum;
    dE = dE < -126 ? -126 : (dE > 92 ? 92 : dE);
    const float f = __int_as_float((127 + dE) << 23);
    const float m1  = (lane == 0) ? f : 1.0f;
    const float m2s = skipw * ((lane <= 1) ? f : 1.0f);

    CTC_STEP(0, bufA, bufB)
    CTC_STEP(1, bufB, bufA)
    CTC_STEP(2, bufA, bufB)
    CTC_STEP(3, bufB, bufA)
    CTC_STEP(4, bufA, bufB)
    CTC_STEP(5, bufB, bufA)
    CTC_STEP(6, bufA, bufB)
    CTC_STEP(7, bufB, bufA)

#pragma unroll
    for (int j = 0; j < G; j++) lpv[j] = lpn[j];
  }

  // Readout: alpha[S-1] (warp (S-1)>>5) and alpha[S-2] (warp (S-2)>>5) live in
  // registers under their own warps' scales; combine in double log space.
  if (s == S - 1) fin[0] = a;
  if (s == S - 2) fin[1] = a;
  __syncthreads();
  if (s == 0) {
    const int w1 = (S - 1) >> 5, w2 = (S - 2) >> 5;
    const double l1 = (fin[0] > 0.0f) ? (log2((double)fin[0]) + (double)sE[w1]) : -4e9;
    const double l2 = (fin[1] > 0.0f) ? (log2((double)fin[1]) + (double)sE[w2]) : -4e9;
    const double m = fmax(l1, l2);
    const double tot = (m + log2(exp2(l1 - m) + exp2(l2 - m))) * 0.6931471805599453;
    g_tot[b] = (float)tot;
  }
}

// Deterministic final reduction (fixed order, no atomics).
__global__ void ctc_reduce_kernel(float* __restrict__ out, int B) {
  if (threadIdx.x == 0 && blockIdx.x == 0) {
    double acc = 0.0;
    for (int b = 0; b < B; b++) acc += (double)g_tot[b];
    out[0] = (float)(-acc);
  }
}

extern "C" void kernel_launch(void* const* d_in, const int* in_sizes, int n_in,
                              void* d_out, int out_size) {
  const float* lp      = (const float*)d_in[0];  // [T, B, V] log-softmax
  const int*   targets = (const int*)d_in[1];    // [B*L]
  const int*   ilen    = (const int*)d_in[2];    // [B]
  (void)n_in; (void)out_size;

  const int B = in_sizes[2];
  const int L = in_sizes[1] / B;
  const int V = 1000;                       // vocab (blank = 0)
  const int S = 2 * L + 1;
  const int NT = ((S + 31) / 32) * 32;      // 288 threads for S=257
  const size_t shmem = (size_t)(2 * (NT + 2) + 2 + (NT >> 5)) * sizeof(float);

  ctc_scan_kernel<<<B, NT, shmem>>>(lp, targets, ilen, B, V, L);
  ctc_reduce_kernel<<<1, 32>>>((float*)d_out, B);
}